// round 1
// baseline (speedup 1.0000x reference)
#include <cuda_runtime.h>

// DeepFilter: out_r = box3x5( xr*fr - xi*fi ),  out_i = box3x5( 2*xr*fi )
// (input and filter are shifted identically per tap in the reference, so the
//  15-tap "deep filter" is exactly a 3(freq) x 5(time) box sum of the
//  pointwise products, with zero padding.)
//
// Shapes: B=8, D=256, T=2048, L=2 (time halo +-2), I=1 (freq halo +-1).
// Output: [B, 2D, T] (out_r channels then out_i channels).

static constexpr int Bn = 8;
static constexpr int Dn = 256;
static constexpr int Tn = 2048;

static constexpr int D_TILE = 32;
static constexpr int T_TILE = 128;
static constexpr int SM_H = D_TILE + 2;   // 34 rows (freq halo +-1)
static constexpr int SM_W = T_TILE + 8;   // 136 cols (time halo +-2, padded to +-4 for f4 alignment)
static constexpr int COL4 = SM_W / 4;     // 34 float4 groups per row
static constexpr int NTHREADS = 256;

__global__ __launch_bounds__(NTHREADS, 2)
void deepfilter_kernel(const float* __restrict__ xr,
                       const float* __restrict__ xi,
                       const float* __restrict__ fr,
                       const float* __restrict__ fi,
                       float* __restrict__ out)
{
    __shared__ float Pr[SM_H][SM_W];
    __shared__ float Pi[SM_H][SM_W];

    const int b   = blockIdx.z;
    const int d0  = blockIdx.y * D_TILE;
    const int t0  = blockIdx.x * T_TILE;
    const int tid = threadIdx.x;

    const size_t base = (size_t)b * Dn * Tn;

    // ---- Phase 1: load 4 inputs, compute pointwise products into SMEM ----
    // Region: d in [d0-1, d0+D_TILE], t in [t0-4, t0+T_TILE+4).
    // Every float4 group is fully in-bounds or fully out (offsets are 4-aligned,
    // Tn divisible by 4), so no per-lane edge handling is needed.
    for (int g = tid; g < SM_H * COL4; g += NTHREADS) {
        const int row = g / COL4;
        const int c4  = g - row * COL4;
        const int d   = d0 - 1 + row;
        const int t   = t0 - 4 + c4 * 4;

        float4 pr = make_float4(0.f, 0.f, 0.f, 0.f);
        float4 pi = make_float4(0.f, 0.f, 0.f, 0.f);

        if ((unsigned)d < (unsigned)Dn && (unsigned)t < (unsigned)Tn) {
            const size_t idx = base + (size_t)d * Tn + t;
            const float4 a = *reinterpret_cast<const float4*>(xr + idx);
            const float4 c = *reinterpret_cast<const float4*>(xi + idx);
            const float4 e = *reinterpret_cast<const float4*>(fr + idx);
            const float4 f = *reinterpret_cast<const float4*>(fi + idx);
            pr.x = a.x * e.x - c.x * f.x;  pi.x = 2.f * a.x * f.x;
            pr.y = a.y * e.y - c.y * f.y;  pi.y = 2.f * a.y * f.y;
            pr.z = a.z * e.z - c.z * f.z;  pi.z = 2.f * a.z * f.z;
            pr.w = a.w * e.w - c.w * f.w;  pi.w = 2.f * a.w * f.w;
        }
        *reinterpret_cast<float4*>(&Pr[row][c4 * 4]) = pr;
        *reinterpret_cast<float4*>(&Pi[row][c4 * 4]) = pi;
    }

    __syncthreads();

    // ---- Phase 2: 3x5 box sum ----
    // Thread (tx, ty): tx = 4-wide t-group (32 groups), ty*4..ty*4+3 = d rows.
    // Stream 6 SMEM freq rows; each contributes to up to 3 of the thread's
    // 4 d-row accumulators (freq 3-tap sharing in registers).
    const int tx = tid & 31;
    const int ty = tid >> 5;
    const int sc = 4 * tx;   // base SMEM col; reads cover cols sc .. sc+11

    float qr[4][8], qi[4][8];
    #pragma unroll
    for (int dl = 0; dl < 4; ++dl)
        #pragma unroll
        for (int j = 0; j < 8; ++j) { qr[dl][j] = 0.f; qi[dl][j] = 0.f; }

    #pragma unroll
    for (int r = 0; r < 6; ++r) {
        const int srow = ty * 4 + r;
        const float4 a0 = *reinterpret_cast<const float4*>(&Pr[srow][sc]);
        const float4 a1 = *reinterpret_cast<const float4*>(&Pr[srow][sc + 4]);
        const float4 a2 = *reinterpret_cast<const float4*>(&Pr[srow][sc + 8]);
        const float4 b0 = *reinterpret_cast<const float4*>(&Pi[srow][sc]);
        const float4 b1 = *reinterpret_cast<const float4*>(&Pi[srow][sc + 4]);
        const float4 b2 = *reinterpret_cast<const float4*>(&Pi[srow][sc + 8]);

        // cols sc+2 .. sc+9 relative to tile: 8 values needed for 4 outputs
        const float vr[8] = {a0.z, a0.w, a1.x, a1.y, a1.z, a1.w, a2.x, a2.y};
        const float vi[8] = {b0.z, b0.w, b1.x, b1.y, b1.z, b1.w, b2.x, b2.y};

        #pragma unroll
        for (int dl = 0; dl < 4; ++dl) {
            if (r >= dl && r <= dl + 2) {   // compile-time after unroll
                #pragma unroll
                for (int j = 0; j < 8; ++j) {
                    qr[dl][j] += vr[j];
                    qi[dl][j] += vi[j];
                }
            }
        }
    }

    // Time-direction 5-tap sums in registers, vectorized stores.
    const size_t ob   = (size_t)b * (2 * Dn) * Tn;
    const int    tout = t0 + 4 * tx;

    #pragma unroll
    for (int dl = 0; dl < 4; ++dl) {
        const int d = d0 + ty * 4 + dl;
        float4 orr, oii;
        orr.x = qr[dl][0] + qr[dl][1] + qr[dl][2] + qr[dl][3] + qr[dl][4];
        orr.y = qr[dl][1] + qr[dl][2] + qr[dl][3] + qr[dl][4] + qr[dl][5];
        orr.z = qr[dl][2] + qr[dl][3] + qr[dl][4] + qr[dl][5] + qr[dl][6];
        orr.w = qr[dl][3] + qr[dl][4] + qr[dl][5] + qr[dl][6] + qr[dl][7];
        oii.x = qi[dl][0] + qi[dl][1] + qi[dl][2] + qi[dl][3] + qi[dl][4];
        oii.y = qi[dl][1] + qi[dl][2] + qi[dl][3] + qi[dl][4] + qi[dl][5];
        oii.z = qi[dl][2] + qi[dl][3] + qi[dl][4] + qi[dl][5] + qi[dl][6];
        oii.w = qi[dl][3] + qi[dl][4] + qi[dl][5] + qi[dl][6] + qi[dl][7];

        const size_t o = ob + (size_t)d * Tn + tout;
        *reinterpret_cast<float4*>(out + o)                        = orr;
        *reinterpret_cast<float4*>(out + o + (size_t)Dn * Tn)      = oii;
    }
}

extern "C" void kernel_launch(void* const* d_in, const int* in_sizes, int n_in,
                              void* d_out, int out_size)
{
    (void)in_sizes; (void)n_in; (void)out_size;
    const float* xr = (const float*)d_in[0];
    const float* xi = (const float*)d_in[1];
    const float* fr = (const float*)d_in[2];
    const float* fi = (const float*)d_in[3];
    float* out = (float*)d_out;
    // d_in[4] = L (=2), d_in[5] = I (=1): fixed for this problem, baked into the kernel.

    dim3 grid(Tn / T_TILE, Dn / D_TILE, Bn);   // (16, 8, 8)
    deepfilter_kernel<<<grid, NTHREADS>>>(xr, xi, fr, fi, out);
}

// round 2
// speedup vs baseline: 1.3050x; 1.3050x over previous
#include <cuda_runtime.h>

// DeepFilter: out_r = box3x5( xr*fr - xi*fi ),  out_i = box3x5( 2*xr*fi )
// 3(freq) x 5(time) box sum of pointwise products with zero padding.
// Shapes: B=8, D=256, T=2048, L=2, I=1. Output [B, 2D, T].

static constexpr int Bn = 8;
static constexpr int Dn = 256;
static constexpr int Tn = 2048;

static constexpr int D_TILE = 16;
static constexpr int T_TILE = 128;
static constexpr int SM_H = D_TILE + 2;   // 18 rows (freq halo +-1)
static constexpr int SM_W = T_TILE + 8;   // 136 cols (time halo +-2, padded to +-4 for f4 align)
static constexpr int COL4 = SM_W / 4;     // 34 float4 groups per row
static constexpr int NTHREADS = 256;

__global__ __launch_bounds__(NTHREADS, 6)
void deepfilter_kernel(const float* __restrict__ xr,
                       const float* __restrict__ xi,
                       const float* __restrict__ fr,
                       const float* __restrict__ fi,
                       float* __restrict__ out)
{
    __shared__ float Pr[SM_H][SM_W];
    __shared__ float Pi[SM_H][SM_W];

    const int b   = blockIdx.z;
    const int d0  = blockIdx.y * D_TILE;
    const int t0  = blockIdx.x * T_TILE;
    const int tid = threadIdx.x;

    const size_t base = (size_t)b * Dn * Tn;

    // ---- Phase 1: load 4 inputs, compute pointwise products into SMEM ----
    // Region: d in [d0-1, d0+D_TILE], t in [t0-4, t0+T_TILE+4).
    // Every float4 group is fully in-bounds or fully out (4-aligned offsets).
    #pragma unroll
    for (int g = tid; g < SM_H * COL4; g += NTHREADS) {
        const int row = g / COL4;
        const int c4  = g - row * COL4;
        const int d   = d0 - 1 + row;
        const int t   = t0 - 4 + c4 * 4;

        float4 pr = make_float4(0.f, 0.f, 0.f, 0.f);
        float4 pi = make_float4(0.f, 0.f, 0.f, 0.f);

        if ((unsigned)d < (unsigned)Dn && (unsigned)t < (unsigned)Tn) {
            const size_t idx = base + (size_t)d * Tn + t;
            const float4 a = *reinterpret_cast<const float4*>(xr + idx);
            const float4 c = *reinterpret_cast<const float4*>(xi + idx);
            const float4 e = *reinterpret_cast<const float4*>(fr + idx);
            const float4 f = *reinterpret_cast<const float4*>(fi + idx);
            pr.x = fmaf(a.x, e.x, -c.x * f.x);  pi.x = 2.f * a.x * f.x;
            pr.y = fmaf(a.y, e.y, -c.y * f.y);  pi.y = 2.f * a.y * f.y;
            pr.z = fmaf(a.z, e.z, -c.z * f.z);  pi.z = 2.f * a.z * f.z;
            pr.w = fmaf(a.w, e.w, -c.w * f.w);  pi.w = 2.f * a.w * f.w;
        }
        *reinterpret_cast<float4*>(&Pr[row][c4 * 4]) = pr;
        *reinterpret_cast<float4*>(&Pi[row][c4 * 4]) = pi;
    }

    __syncthreads();

    // ---- Phase 2: 3x5 box sum, time-sum first (low register pressure) ----
    // Thread (tx, ty): tx = 4-wide t-group (32), ty in [0,8): d-rows 2*ty, 2*ty+1.
    // Stream 4 SMEM freq rows; per row compute 4 sliding time-sums, then
    // accumulate into the 2 freq-window accumulators.
    const int tx = tid & 31;
    const int ty = tid >> 5;
    const int sc = 4 * tx;   // reads cover SMEM cols sc .. sc+11

    float qr[2][4], qi[2][4];
    #pragma unroll
    for (int dl = 0; dl < 2; ++dl)
        #pragma unroll
        for (int j = 0; j < 4; ++j) { qr[dl][j] = 0.f; qi[dl][j] = 0.f; }

    #pragma unroll
    for (int r = 0; r < 4; ++r) {
        const int srow = 2 * ty + r;
        const float4 a0 = *reinterpret_cast<const float4*>(&Pr[srow][sc]);
        const float4 a1 = *reinterpret_cast<const float4*>(&Pr[srow][sc + 4]);
        const float4 a2 = *reinterpret_cast<const float4*>(&Pr[srow][sc + 8]);
        const float4 b0 = *reinterpret_cast<const float4*>(&Pi[srow][sc]);
        const float4 b1 = *reinterpret_cast<const float4*>(&Pi[srow][sc + 4]);
        const float4 b2 = *reinterpret_cast<const float4*>(&Pi[srow][sc + 8]);

        // values at SMEM cols sc+2 .. sc+9 (t_out-2 .. t_out+5)
        // sliding 5-tap sums: sr[j] = sum cols sc+2+j .. sc+6+j
        float sr0 = a0.z + a0.w + a1.x + a1.y + a1.z;
        float sr1 = sr0 - a0.z + a1.w;
        float sr2 = sr1 - a0.w + a2.x;
        float sr3 = sr2 - a1.x + a2.y;
        float si0 = b0.z + b0.w + b1.x + b1.y + b1.z;
        float si1 = si0 - b0.z + b1.w;
        float si2 = si1 - b0.w + b2.x;
        float si3 = si2 - b1.x + b2.y;

        // freq windows: output row dl uses smem rows 2ty+dl .. 2ty+dl+2
        #pragma unroll
        for (int dl = 0; dl < 2; ++dl) {
            if (r >= dl && r <= dl + 2) {   // compile-time after unroll
                qr[dl][0] += sr0; qr[dl][1] += sr1; qr[dl][2] += sr2; qr[dl][3] += sr3;
                qi[dl][0] += si0; qi[dl][1] += si1; qi[dl][2] += si2; qi[dl][3] += si3;
            }
        }
    }

    const size_t ob   = (size_t)b * (2 * Dn) * Tn;
    const int    tout = t0 + 4 * tx;

    #pragma unroll
    for (int dl = 0; dl < 2; ++dl) {
        const int d = d0 + 2 * ty + dl;
        const size_t o = ob + (size_t)d * Tn + tout;
        float4 orr = make_float4(qr[dl][0], qr[dl][1], qr[dl][2], qr[dl][3]);
        float4 oii = make_float4(qi[dl][0], qi[dl][1], qi[dl][2], qi[dl][3]);
        __stcs(reinterpret_cast<float4*>(out + o), orr);
        __stcs(reinterpret_cast<float4*>(out + o + (size_t)Dn * Tn), oii);
    }
}

extern "C" void kernel_launch(void* const* d_in, const int* in_sizes, int n_in,
                              void* d_out, int out_size)
{
    (void)in_sizes; (void)n_in; (void)out_size;
    const float* xr = (const float*)d_in[0];
    const float* xi = (const float*)d_in[1];
    const float* fr = (const float*)d_in[2];
    const float* fi = (const float*)d_in[3];
    float* out = (float*)d_out;

    dim3 grid(Tn / T_TILE, Dn / D_TILE, Bn);   // (16, 16, 8)
    deepfilter_kernel<<<grid, NTHREADS>>>(xr, xi, fr, fi, out);
}

// round 3
// speedup vs baseline: 1.4262x; 1.0929x over previous
#include <cuda_runtime.h>

// DeepFilter: out_r = box3x5( xr*fr - xi*fi ),  out_i = box3x5( 2*xr*fi )
// Smem-free version: time halo via warp shuffles, freq reuse via per-warp
// row strips (each warp owns 2 output d-rows, streams 4 input rows).
// Shapes: B=8, D=256, T=2048, L=2, I=1. Output [B, 2D, T].

static constexpr int Bn = 8;
static constexpr int Dn = 256;
static constexpr int Tn = 2048;

static constexpr int NTHREADS = 128;           // 4 warps
static constexpr int T_TILE   = 128;           // 32 lanes x float4
static constexpr int D_TILE   = (NTHREADS / 32) * 2;  // 8 output rows / block

__device__ __forceinline__ float4 ld4(const float* p) {
    return *reinterpret_cast<const float4*>(p);
}
__device__ __forceinline__ float2 ld2(const float* p) {
    return *reinterpret_cast<const float2*>(p);
}

__global__ __launch_bounds__(NTHREADS, 9)
void deepfilter_kernel(const float* __restrict__ xr,
                       const float* __restrict__ xi,
                       const float* __restrict__ fr,
                       const float* __restrict__ fi,
                       float* __restrict__ out)
{
    const int b    = blockIdx.z;
    const int t0   = blockIdx.x * T_TILE;
    const int d0   = blockIdx.y * D_TILE;
    const int warp = threadIdx.x >> 5;
    const int lane = threadIdx.x & 31;
    const int t    = t0 + 4 * lane;

    const size_t base  = (size_t)b * Dn * Tn;
    const int    dbase = d0 + 2 * warp;        // output rows dbase, dbase+1

    float4 Qr0 = {0,0,0,0}, Qi0 = {0,0,0,0};
    float4 Qr1 = {0,0,0,0}, Qi1 = {0,0,0,0};

    // Warp-edge time halo: lane 0 needs cols t0-2,t0-1; lane 31 needs
    // t0+128,t0+129. Both are 8B-aligned float2 loads, used identically.
    const int  ht      = (lane == 0) ? (t0 - 2) : (t0 + T_TILE);
    const bool hlane   = (lane == 0) | (lane == 31);
    const bool hok_t   = (ht >= 0) & (ht < Tn);

    #pragma unroll
    for (int r = 0; r < 4; ++r) {
        const int  d   = dbase - 1 + r;
        const bool dok = (unsigned)d < (unsigned)Dn;

        float4 a = {0,0,0,0}, c = {0,0,0,0}, e = {0,0,0,0}, f = {0,0,0,0};
        float2 ha = {0,0}, hc = {0,0}, he = {0,0}, hf = {0,0};

        if (dok) {
            const size_t idx = base + (size_t)d * Tn + t;
            a = ld4(xr + idx); c = ld4(xi + idx);
            e = ld4(fr + idx); f = ld4(fi + idx);
            if (hlane & hok_t) {
                const size_t hidx = base + (size_t)d * Tn + ht;
                ha = ld2(xr + hidx); hc = ld2(xi + hidx);
                he = ld2(fr + hidx); hf = ld2(fi + hidx);
            }
        }

        // pointwise products for this lane's 4 cols
        const float pr0 = fmaf(a.x, e.x, -c.x * f.x);
        const float pr1 = fmaf(a.y, e.y, -c.y * f.y);
        const float pr2 = fmaf(a.z, e.z, -c.z * f.z);
        const float pr3 = fmaf(a.w, e.w, -c.w * f.w);
        const float pi0 = 2.f * a.x * f.x;
        const float pi1 = 2.f * a.y * f.y;
        const float pi2 = 2.f * a.z * f.z;
        const float pi3 = 2.f * a.w * f.w;

        // halo products (lane0: positions -2,-1 ; lane31: positions +4,+5)
        const float hpr0 = fmaf(ha.x, he.x, -hc.x * hf.x);
        const float hpr1 = fmaf(ha.y, he.y, -hc.y * hf.y);
        const float hpi0 = 2.f * ha.x * hf.x;
        const float hpi1 = 2.f * ha.y * hf.y;

        // neighbor exchange: lm* = p[-2],p[-1]; rp* = p[+4],p[+5]
        float lmr2 = __shfl_up_sync(0xffffffffu, pr2, 1);
        float lmr1 = __shfl_up_sync(0xffffffffu, pr3, 1);
        float rpr4 = __shfl_down_sync(0xffffffffu, pr0, 1);
        float rpr5 = __shfl_down_sync(0xffffffffu, pr1, 1);
        float lmi2 = __shfl_up_sync(0xffffffffu, pi2, 1);
        float lmi1 = __shfl_up_sync(0xffffffffu, pi3, 1);
        float rpi4 = __shfl_down_sync(0xffffffffu, pi0, 1);
        float rpi5 = __shfl_down_sync(0xffffffffu, pi1, 1);
        if (lane == 0)  { lmr2 = hpr0; lmr1 = hpr1; lmi2 = hpi0; lmi1 = hpi1; }
        if (lane == 31) { rpr4 = hpr0; rpr5 = hpr1; rpi4 = hpi0; rpi5 = hpi1; }

        // sliding 5-tap time sums
        const float sr0 = lmr2 + lmr1 + pr0 + pr1 + pr2;
        const float sr1 = sr0 - lmr2 + pr3;
        const float sr2 = sr1 - lmr1 + rpr4;
        const float sr3 = sr2 - pr0 + rpr5;
        const float si0 = lmi2 + lmi1 + pi0 + pi1 + pi2;
        const float si1 = si0 - lmi2 + pi3;
        const float si2 = si1 - lmi1 + rpi4;
        const float si3 = si2 - pi0 + rpi5;

        // freq 3-tap accumulation (compile-time predicates after unroll)
        if (r <= 2) {
            Qr0.x += sr0; Qr0.y += sr1; Qr0.z += sr2; Qr0.w += sr3;
            Qi0.x += si0; Qi0.y += si1; Qi0.z += si2; Qi0.w += si3;
        }
        if (r >= 1) {
            Qr1.x += sr0; Qr1.y += sr1; Qr1.z += sr2; Qr1.w += sr3;
            Qi1.x += si0; Qi1.y += si1; Qi1.z += si2; Qi1.w += si3;
        }
    }

    const size_t ob = (size_t)b * (2 * Dn) * Tn;
    const size_t o0 = ob + (size_t)dbase * Tn + t;
    const size_t oI = (size_t)Dn * Tn;
    __stcs(reinterpret_cast<float4*>(out + o0),          Qr0);
    __stcs(reinterpret_cast<float4*>(out + o0 + oI),     Qi0);
    __stcs(reinterpret_cast<float4*>(out + o0 + Tn),     Qr1);
    __stcs(reinterpret_cast<float4*>(out + o0 + Tn + oI), Qi1);
}

extern "C" void kernel_launch(void* const* d_in, const int* in_sizes, int n_in,
                              void* d_out, int out_size)
{
    (void)in_sizes; (void)n_in; (void)out_size;
    const float* xr = (const float*)d_in[0];
    const float* xi = (const float*)d_in[1];
    const float* fr = (const float*)d_in[2];
    const float* fi = (const float*)d_in[3];
    float* out = (float*)d_out;

    dim3 grid(Tn / T_TILE, Dn / D_TILE, Bn);   // (16, 32, 8) = 4096 blocks
    deepfilter_kernel<<<grid, NTHREADS>>>(xr, xi, fr, fi, out);
}

// round 4
// speedup vs baseline: 1.7059x; 1.1961x over previous
#include <cuda_runtime.h>

// DeepFilter: out_r = box3x5( xr*fr - xi*fi ),  out_i = 2 * box3x5( xr*fi )
// Smem-free: time halo via warp shuffles, freq direction via a rolling
// 3-row window. Each warp owns 8 output d-rows and streams 10 input rows.
// Shapes: B=8, D=256, T=2048, L=2, I=1. Output [B, 2D, T].

static constexpr int Bn = 8;
static constexpr int Dn = 256;
static constexpr int Tn = 2048;

static constexpr int NTHREADS = 128;   // 4 warps
static constexpr int T_TILE   = 128;   // 32 lanes x float4
static constexpr int D_STRIP  = 8;     // output rows per warp
static constexpr int D_TILE   = (NTHREADS / 32) * D_STRIP;   // 32 rows / block

__device__ __forceinline__ float4 ld4(const float* p) {
    return *reinterpret_cast<const float4*>(p);
}
__device__ __forceinline__ float2 ld2(const float* p) {
    return *reinterpret_cast<const float2*>(p);
}

__global__ __launch_bounds__(NTHREADS, 8)
void deepfilter_kernel(const float* __restrict__ xr,
                       const float* __restrict__ xi,
                       const float* __restrict__ fr,
                       const float* __restrict__ fi,
                       float* __restrict__ out)
{
    const int b    = blockIdx.z;
    const int t0   = blockIdx.x * T_TILE;
    const int d0   = blockIdx.y * D_TILE;
    const int warp = threadIdx.x >> 5;
    const int lane = threadIdx.x & 31;
    const int t    = t0 + 4 * lane;

    const size_t base  = (size_t)b * Dn * Tn;
    const int    dbase = d0 + D_STRIP * warp;   // output rows dbase .. dbase+7

    // Warp-edge time halo: lane 0 needs cols t0-2,t0-1; lane 31 needs
    // t0+128,t0+129. Both are 8B-aligned float2 loads used identically.
    const int  ht    = (lane == 0) ? (t0 - 2) : (t0 + T_TILE);
    const bool hlane = (lane == 0) | (lane == 31);
    const bool hok_t = (ht >= 0) & (ht < Tn);

    // rolling time-sum state: s[r-1], s[r-2]
    float4 m1r = {0,0,0,0}, m1i = {0,0,0,0};
    float4 m2r = {0,0,0,0}, m2i = {0,0,0,0};

    const size_t ob = (size_t)b * (2 * Dn) * Tn;
    const size_t oI = (size_t)Dn * Tn;

    #pragma unroll
    for (int r = 0; r < D_STRIP + 2; ++r) {
        const int  d   = dbase - 1 + r;
        const bool dok = (unsigned)d < (unsigned)Dn;

        float4 a = {0,0,0,0}, c = {0,0,0,0}, e = {0,0,0,0}, f = {0,0,0,0};
        float2 ha = {0,0}, hc = {0,0}, he = {0,0}, hf = {0,0};

        if (dok) {
            const size_t idx = base + (size_t)d * Tn + t;
            a = ld4(xr + idx); c = ld4(xi + idx);
            e = ld4(fr + idx); f = ld4(fi + idx);
            if (hlane & hok_t) {
                const size_t hidx = base + (size_t)d * Tn + ht;
                ha = ld2(xr + hidx); hc = ld2(xi + hidx);
                he = ld2(fr + hidx); hf = ld2(fi + hidx);
            }
        }

        // pointwise products (imag part WITHOUT the 2x — folded into store)
        const float pr0 = fmaf(a.x, e.x, -c.x * f.x);
        const float pr1 = fmaf(a.y, e.y, -c.y * f.y);
        const float pr2 = fmaf(a.z, e.z, -c.z * f.z);
        const float pr3 = fmaf(a.w, e.w, -c.w * f.w);
        const float pi0 = a.x * f.x;
        const float pi1 = a.y * f.y;
        const float pi2 = a.z * f.z;
        const float pi3 = a.w * f.w;

        // halo products (lane0: t-2,t-1 ; lane31: t+4,t+5)
        const float hpr0 = fmaf(ha.x, he.x, -hc.x * hf.x);
        const float hpr1 = fmaf(ha.y, he.y, -hc.y * hf.y);
        const float hpi0 = ha.x * hf.x;
        const float hpi1 = ha.y * hf.y;

        // neighbor exchange: lm* = p[-2],p[-1]; rp* = p[+4],p[+5]
        float lmr2 = __shfl_up_sync(0xffffffffu, pr2, 1);
        float lmr1 = __shfl_up_sync(0xffffffffu, pr3, 1);
        float rpr4 = __shfl_down_sync(0xffffffffu, pr0, 1);
        float rpr5 = __shfl_down_sync(0xffffffffu, pr1, 1);
        float lmi2 = __shfl_up_sync(0xffffffffu, pi2, 1);
        float lmi1 = __shfl_up_sync(0xffffffffu, pi3, 1);
        float rpi4 = __shfl_down_sync(0xffffffffu, pi0, 1);
        float rpi5 = __shfl_down_sync(0xffffffffu, pi1, 1);
        if (lane == 0)  { lmr2 = hpr0; lmr1 = hpr1; lmi2 = hpi0; lmi1 = hpi1; }
        if (lane == 31) { rpr4 = hpr0; rpr5 = hpr1; rpi4 = hpi0; rpi5 = hpi1; }

        // sliding 5-tap time sums for this input row
        float4 sr, si;
        sr.x = lmr2 + lmr1 + pr0 + pr1 + pr2;
        sr.y = sr.x - lmr2 + pr3;
        sr.z = sr.y - lmr1 + rpr4;
        sr.w = sr.z - pr0 + rpr5;
        si.x = lmi2 + lmi1 + pi0 + pi1 + pi2;
        si.y = si.x - lmi2 + pi3;
        si.z = si.y - lmi1 + rpi4;
        si.w = si.z - pi0 + rpi5;

        // rolling 3-row freq sum: emit output row dbase + r - 2
        if (r >= 2) {
            const int d_out = dbase + r - 2;
            float4 orr, oii;
            orr.x = m2r.x + m1r.x + sr.x;
            orr.y = m2r.y + m1r.y + sr.y;
            orr.z = m2r.z + m1r.z + sr.z;
            orr.w = m2r.w + m1r.w + sr.w;
            oii.x = 2.f * (m2i.x + m1i.x + si.x);
            oii.y = 2.f * (m2i.y + m1i.y + si.y);
            oii.z = 2.f * (m2i.z + m1i.z + si.z);
            oii.w = 2.f * (m2i.w + m1i.w + si.w);
            const size_t o = ob + (size_t)d_out * Tn + t;
            __stcs(reinterpret_cast<float4*>(out + o),      orr);
            __stcs(reinterpret_cast<float4*>(out + o + oI), oii);
        }
        m2r = m1r; m2i = m1i;
        m1r = sr;  m1i = si;
    }
}

extern "C" void kernel_launch(void* const* d_in, const int* in_sizes, int n_in,
                              void* d_out, int out_size)
{
    (void)in_sizes; (void)n_in; (void)out_size;
    const float* xr = (const float*)d_in[0];
    const float* xi = (const float*)d_in[1];
    const float* fr = (const float*)d_in[2];
    const float* fi = (const float*)d_in[3];
    float* out = (float*)d_out;

    dim3 grid(Tn / T_TILE, Dn / D_TILE, Bn);   // (16, 8, 8) = 1024 blocks
    deepfilter_kernel<<<grid, NTHREADS>>>(xr, xi, fr, fi, out);
}